// round 1
// baseline (speedup 1.0000x reference)
#include <cuda_runtime.h>
#include <cstdint>

// Problem constants (fixed by setup_inputs)
#define N      4096
#define NB     512      // batch
#define KDIM   2
#define NSTEPS 64
#define DT     0.1f
#define OMDT   0.9f     // 1 - DT

// ---------------- device scratch (no allocations allowed) ----------------
__device__ float g_Wp[(size_t)N * N];        // dense P22 (67 MB)
__device__ float g_hA[(size_t)N * NB];       // ping-pong h state
__device__ float g_hB[(size_t)N * NB];
__device__ float g_xA[2 * NB];               // ping-pong x state
__device__ float g_xB[2 * NB];
__device__ float g_zhpart[32 * NB];          // partial Z·h reductions
__device__ float g_cax[NB];                  // DT * (C@A) @ x  (per batch)

// ---------------- build Wp = P22 ----------------
// Wp[i][j] = DT*W[i][j] + cb*M[i]*Z[j] + DT*sum_r U[i][r]*V[j][r] + (i==j)*0.9
__global__ void build_wp(const float* __restrict__ W, const float* __restrict__ Mv,
                         const float* __restrict__ Z, const float* __restrict__ U,
                         const float* __restrict__ V, const float* __restrict__ Bm,
                         const float* __restrict__ C)
{
    int j = blockIdx.x * 256 + threadIdx.x;
    int i = blockIdx.y;
    float cb = C[0] * Bm[0] + C[1] * Bm[1];
    float4 u = *reinterpret_cast<const float4*>(U + (size_t)i * 4);
    float4 v = *reinterpret_cast<const float4*>(V + (size_t)j * 4);
    float uv = u.x * v.x + u.y * v.y + u.z * v.z + u.w * v.w;
    float val = DT * W[(size_t)i * N + j] + cb * Mv[i] * Z[j] + DT * uv;
    if (i == j) val += OMDT;
    g_Wp[(size_t)i * N + j] = val;
}

// ---------------- initial state copy ----------------
__global__ void init_state(const float* __restrict__ x0, const float* __restrict__ x1,
                           const float* __restrict__ h0)
{
    int idx = blockIdx.x * 256 + threadIdx.x;
    if (idx < N * NB) g_hA[idx] = h0[idx];
    if (idx < NB) { g_xA[idx] = x0[idx]; g_xA[NB + idx] = x1[idx]; }
}

// ---------------- per-step: Z·h partial reduction fused with traj h-rows write ----------------
// grid (32 j-chunks, 4 b-tiles), 128 threads
__global__ void zh_traj(int cur, const float* __restrict__ Z, float* __restrict__ traj_t)
{
    const float* __restrict__ h = cur ? g_hB : g_hA;
    int b  = blockIdx.y * 128 + threadIdx.x;
    int j0 = blockIdx.x * 128;
    float s = 0.0f;
#pragma unroll 8
    for (int jj = 0; jj < 128; ++jj) {
        int j = j0 + jj;
        float v = h[(size_t)j * NB + b];
        s += Z[j] * v;
        traj_t[(size_t)(2 + j) * NB + b] = v;
    }
    g_zhpart[blockIdx.x * NB + b] = s;
}

// ---------------- per-step: finish zh, write con + traj x-rows, update x, compute cax ----------------
// 1 block, 512 threads
__global__ void xcon_step(int cur, const float* __restrict__ A, const float* __restrict__ Bm,
                          const float* __restrict__ C, float* __restrict__ traj_t,
                          float* __restrict__ con_t)
{
    const float* __restrict__ xc = cur ? g_xB : g_xA;
    float* __restrict__ xn       = cur ? g_xA : g_xB;
    int b = threadIdx.x;
    float zh = 0.0f;
#pragma unroll
    for (int c = 0; c < 32; ++c) zh += g_zhpart[c * NB + b];
    float x0 = xc[b], x1 = xc[NB + b];
    // traj x rows (pre-step state)
    traj_t[b]      = x0;
    traj_t[NB + b] = x1;
    // con = Bmat[1] * (Z @ h)
    con_t[b] = Bm[1] * zh;
    // new_x = A @ x + Bmat * zh
    xn[b]      = A[0] * x0 + A[1] * x1 + Bm[0] * zh;
    xn[NB + b] = A[2] * x0 + A[3] * x1 + Bm[1] * zh;
    // cax = DT * (C@A) @ x  (used by GEMM epilogue: + M[i]*cax[b])
    float ca0 = C[0] * A[0] + C[1] * A[2];
    float ca1 = C[0] * A[1] + C[1] * A[3];
    g_cax[b] = DT * (ca0 * x0 + ca1 * x1);
}

// ---------------- main GEMM: h_next = Wp @ h + M ⊗ cax ----------------
// 128x128 tile, BK=16, 256 threads, 8x8 per-thread microtile
#define GBM 128
#define GBN 128
#define GBK 16

__global__ __launch_bounds__(256) void gemm_step(int cur, const float* __restrict__ Mv)
{
    const float* __restrict__ h  = cur ? g_hB : g_hA;
    float* __restrict__ ho       = cur ? g_hA : g_hB;

    __shared__ float As[GBK][GBM];   // transposed A tile
    __shared__ float Bs[GBK][GBN];

    int tid = threadIdx.x;
    int bx = blockIdx.x;             // n tile: 0..3
    int by = blockIdx.y;             // m tile: 0..31
    int arow0 = by * GBM;
    int bcol0 = bx * GBN;

    int a_r  = tid >> 2;             // 0..63
    int a_c4 = tid & 3;              // float4 index within 16 cols
    int b_r  = tid >> 5;             // 0..7
    int b_c4 = tid & 31;             // float4 index within 128 cols

    int ty = tid >> 4;               // 0..15
    int tx = tid & 15;               // 0..15

    float acc[8][8];
#pragma unroll
    for (int i = 0; i < 8; ++i)
#pragma unroll
        for (int j = 0; j < 8; ++j) acc[i][j] = 0.0f;

    for (int k0 = 0; k0 < N; k0 += GBK) {
#pragma unroll
        for (int it = 0; it < 2; ++it) {
            int r = a_r + it * 64;
            float4 v = *reinterpret_cast<const float4*>(
                g_Wp + (size_t)(arow0 + r) * N + k0 + a_c4 * 4);
            As[a_c4 * 4 + 0][r] = v.x;
            As[a_c4 * 4 + 1][r] = v.y;
            As[a_c4 * 4 + 2][r] = v.z;
            As[a_c4 * 4 + 3][r] = v.w;
        }
#pragma unroll
        for (int it = 0; it < 2; ++it) {
            int r = b_r + it * 8;
            float4 v = *reinterpret_cast<const float4*>(
                h + (size_t)(k0 + r) * NB + bcol0 + b_c4 * 4);
            *reinterpret_cast<float4*>(&Bs[r][b_c4 * 4]) = v;
        }
        __syncthreads();

#pragma unroll
        for (int kk = 0; kk < GBK; ++kk) {
            float ra[8], rb[8];
#pragma unroll
            for (int i = 0; i < 8; ++i) ra[i] = As[kk][ty * 8 + i];
#pragma unroll
            for (int j = 0; j < 8; ++j) rb[j] = Bs[kk][tx * 8 + j];
#pragma unroll
            for (int i = 0; i < 8; ++i)
#pragma unroll
                for (int j = 0; j < 8; ++j)
                    acc[i][j] += ra[i] * rb[j];
        }
        __syncthreads();
    }

    // epilogue: + M[i]*cax[b], write h_next
#pragma unroll
    for (int i = 0; i < 8; ++i) {
        int row = arow0 + ty * 8 + i;
        float mi = Mv[row];
#pragma unroll
        for (int j = 0; j < 8; j += 4) {
            int col = bcol0 + tx * 8 + j;
            float4 cx = *reinterpret_cast<const float4*>(g_cax + col);
            float4 o;
            o.x = acc[i][j]     + mi * cx.x;
            o.y = acc[i][j + 1] + mi * cx.y;
            o.z = acc[i][j + 2] + mi * cx.z;
            o.w = acc[i][j + 3] + mi * cx.w;
            *reinterpret_cast<float4*>(ho + (size_t)row * NB + col) = o;
        }
    }
}

// ---------------- launch ----------------
extern "C" void kernel_launch(void* const* d_in, const int* in_sizes, int n_in,
                              void* d_out, int out_size)
{
    const float* x0 = (const float*)d_in[0];
    const float* x1 = (const float*)d_in[1];
    const float* h0 = (const float*)d_in[2];
    const float* A  = (const float*)d_in[3];
    const float* Bm = (const float*)d_in[4];
    const float* C  = (const float*)d_in[5];
    const float* M  = (const float*)d_in[6];
    const float* Z  = (const float*)d_in[7];
    const float* U  = (const float*)d_in[8];
    const float* V  = (const float*)d_in[9];
    const float* W  = (const float*)d_in[10];
    (void)in_sizes; (void)n_in; (void)out_size;

    float* out = (float*)d_out;
    const size_t TRAJ_STRIDE = (size_t)(N + 2) * NB;       // 4098*512
    const size_t CON_BASE    = (size_t)NSTEPS * TRAJ_STRIDE;

    build_wp<<<dim3(N / 256, N), 256>>>(W, M, Z, U, V, Bm, C);
    init_state<<<(N * NB + 255) / 256, 256>>>(x0, x1, h0);

    for (int t = 0; t < NSTEPS; ++t) {
        int cur = t & 1;
        float* traj_t = out + (size_t)t * TRAJ_STRIDE;
        float* con_t  = out + CON_BASE + (size_t)t * NB;
        zh_traj<<<dim3(32, 4), 128>>>(cur, Z, traj_t);
        xcon_step<<<1, 512>>>(cur, A, Bm, C, traj_t, con_t);
        if (t < NSTEPS - 1)
            gemm_step<<<dim3(NB / GBN, N / GBM), 256>>>(cur, M);
    }
}

// round 3
// speedup vs baseline: 2.9514x; 2.9514x over previous
#include <cuda_runtime.h>
#include <cuda_bf16.h>
#include <cstdint>

// ---------------- problem constants ----------------
#define N      4096
#define NB     512
#define NSTEPS 64
#define DT     0.1f
#define OMDT   0.9f

#define TRAJ    ((size_t)(N + 2) * NB)
#define CONBASE ((size_t)NSTEPS * TRAJ)

// ---------------- GEMM tiling ----------------
#define BM 128
#define BN 128
#define BK 32
#define STAGES 4
#define ROWB   80                       // padded row: 32 bf16 + 8 pad = 80 bytes
#define MATB   (128 * ROWB)             // 10240 bytes per matrix tile
#define STAGEB (4 * MATB)               // Ah, Al, Bh, Bl
#define HDR    2048
#define SMEMSZ (HDR + STAGES * STAGEB)  // 2048 + 163840 = 165888
#define KSTEPS (N / BK)                 // 128
#define CSTRIDE 132                     // Cs row stride (floats), 16B-friendly

// ---------------- device scratch ----------------
__device__ __align__(256) __nv_bfloat16 g_Wh[(size_t)N * N];
__device__ __align__(256) __nv_bfloat16 g_Wl[(size_t)N * N];
__device__ __align__(256) __nv_bfloat16 g_hh[2][(size_t)NB * N];   // h^T hi  [b][k]
__device__ __align__(256) __nv_bfloat16 g_hl[2][(size_t)NB * N];   // h^T lo
__device__ float g_x[2][2 * NB];
__device__ float g_zp[2][64 * NB];       // 64 partial Z·h chunks per batch

// ---------------- helpers ----------------
__device__ __forceinline__ uint32_t s2u(const void* p) {
    uint32_t a;
    asm("{ .reg .u64 t; cvta.to.shared.u64 t, %1; cvt.u32.u64 %0, t; }" : "=r"(a) : "l"(p));
    return a;
}
__device__ __forceinline__ void cp16(uint32_t s, const void* g) {
    asm volatile("cp.async.cg.shared.global [%0], [%1], 16;" :: "r"(s), "l"(g));
}
#define CPCOMMIT() asm volatile("cp.async.commit_group;" ::: "memory")
#define CPWAIT2()  asm volatile("cp.async.wait_group 2;" ::: "memory")

#define MMA(c, a0, a1, a2, a3, b0, b1) \
    asm volatile( \
        "mma.sync.aligned.m16n8k16.row.col.f32.bf16.bf16.f32 " \
        "{%0,%1,%2,%3},{%4,%5,%6,%7},{%8,%9},{%0,%1,%2,%3};" \
        : "+f"((c)[0]), "+f"((c)[1]), "+f"((c)[2]), "+f"((c)[3]) \
        : "r"(a0), "r"(a1), "r"(a2), "r"(a3), "r"(b0), "r"(b1))

// ---------------- one-time build kernels ----------------
__global__ void build_wp(const float* __restrict__ W, const float* __restrict__ Mv,
                         const float* __restrict__ Z, const float* __restrict__ U,
                         const float* __restrict__ V, const float* __restrict__ Bm,
                         const float* __restrict__ C)
{
    int j = blockIdx.x * 256 + threadIdx.x;
    int i = blockIdx.y;
    float cb = C[0] * Bm[0] + C[1] * Bm[1];
    float4 u = *reinterpret_cast<const float4*>(U + (size_t)i * 4);
    float4 v = *reinterpret_cast<const float4*>(V + (size_t)j * 4);
    float uv = u.x * v.x + u.y * v.y + u.z * v.z + u.w * v.w;
    float val = DT * W[(size_t)i * N + j] + cb * Mv[i] * Z[j] + DT * uv;
    if (i == j) val += OMDT;
    __nv_bfloat16 hi = __float2bfloat16(val);
    float lo = val - __bfloat162float(hi);
    size_t a = (size_t)i * N + j;
    g_Wh[a] = hi;
    g_Wl[a] = __float2bfloat16(lo);
}

// transpose + split h0; also write traj_0 h rows
__global__ void init_h(const float* __restrict__ h0, float* __restrict__ out)
{
    __shared__ float t[32][33];
    int jb = blockIdx.x * 32, bb = blockIdx.y * 32;
    int tx = threadIdx.x, ty = threadIdx.y;  // 32 x 8
#pragma unroll
    for (int r = 0; r < 4; ++r) {
        int j = jb + ty + r * 8;
        float v = h0[(size_t)j * NB + bb + tx];
        t[ty + r * 8][tx] = v;
        out[(size_t)(2 + j) * NB + bb + tx] = v;
    }
    __syncthreads();
#pragma unroll
    for (int r = 0; r < 4; ++r) {
        int b = bb + ty + r * 8;
        int j = jb + tx;
        float v = t[tx][ty + r * 8];
        __nv_bfloat16 hi = __float2bfloat16(v);
        size_t a = (size_t)b * N + j;
        g_hh[0][a] = hi;
        g_hl[0][a] = __float2bfloat16(v - __bfloat162float(hi));
    }
}

__global__ void init_zx(const float* __restrict__ h0, const float* __restrict__ Z,
                        const float* __restrict__ x0, const float* __restrict__ x1)
{
    int b = blockIdx.y * 128 + threadIdx.x;
    int j0 = blockIdx.x * 64;
    float s = 0.0f;
#pragma unroll 8
    for (int jj = 0; jj < 64; ++jj)
        s += Z[j0 + jj] * h0[(size_t)(j0 + jj) * NB + b];
    g_zp[0][blockIdx.x * NB + b] = s;
    if (blockIdx.x == 0 && blockIdx.y == 0) {
        for (int bb = threadIdx.x; bb < NB; bb += 128) {
            g_x[0][bb]      = x0[bb];
            g_x[0][NB + bb] = x1[bb];
        }
    }
}

__global__ void final_xcon(const float* __restrict__ Bm, float* __restrict__ out)
{
    int b = threadIdx.x;  // 512
    float zh = 0.0f;
#pragma unroll
    for (int c = 0; c < 64; ++c) zh += g_zp[1][c * NB + b];
    const float* xc = g_x[1];
    out[(size_t)63 * TRAJ + b]      = xc[b];
    out[(size_t)63 * TRAJ + NB + b] = xc[NB + b];
    out[CONBASE + (size_t)63 * NB + b] = Bm[1] * zh;
}

// ---------------- fused step kernel ----------------
// h_next = Wp @ h + M ⊗ cax  via 3-product bf16 split on mma.sync (HMMA).
__global__ void __launch_bounds__(256, 1)
gemm_step(int cur, const float* __restrict__ Ain, const float* __restrict__ Bm,
          const float* __restrict__ Cin, const float* __restrict__ Mv,
          const float* __restrict__ Zv, float* __restrict__ out, int t)
{
    extern __shared__ char smem[];
    const uint32_t sb = s2u(smem);
    const int tid = threadIdx.x;
    const int lane = tid & 31;
    const int wid = tid >> 5;
    const int wm = wid >> 2, wn = wid & 3;      // 2 x 4 warp grid
    const int nt = blockIdx.x, mt = blockIdx.y; // (4, 32)
    const int m0 = mt * BM, b0t = nt * BN;
    const int nxt = cur ^ 1;

    const __nv_bfloat16* __restrict__ hh = g_hh[cur];
    const __nv_bfloat16* __restrict__ hl = g_hl[cur];
    __nv_bfloat16* __restrict__ oh = g_hh[nxt];
    __nv_bfloat16* __restrict__ ol = g_hl[nxt];

    float* cax_s = reinterpret_cast<float*>(smem + 64);     // 128 floats
    float* m_s   = reinterpret_cast<float*>(smem + 640);    // 128 floats
    float* z_s   = reinterpret_cast<float*>(smem + 1216);   // 128 floats

    // ---- prologue: cax for this CTA's batch cols; CTA(0,0) global x/con ----
    {
        const float* zp = g_zp[cur];
        const float* xc = g_x[cur];
        if (tid < 128) {
            float ca0 = Cin[0] * Ain[0] + Cin[1] * Ain[2];
            float ca1 = Cin[0] * Ain[1] + Cin[1] * Ain[3];
            int b = b0t + tid;
            float zh = 0.0f;
#pragma unroll
            for (int c = 0; c < 64; ++c) zh += zp[c * NB + b];
            cax_s[tid] = DT * (ca0 * xc[b] + ca1 * xc[NB + b]);
            m_s[tid] = Mv[m0 + tid];
            z_s[tid] = Zv[m0 + tid];
        }
        if (mt == 0 && nt == 0) {
            float* xn = g_x[nxt];
            float a0 = Ain[0], a1 = Ain[1], a2 = Ain[2], a3 = Ain[3];
            float bm0 = Bm[0], bm1 = Bm[1];
#pragma unroll
            for (int k = 0; k < 2; ++k) {
                int bb = tid + k * 256;
                float z2 = 0.0f;
#pragma unroll
                for (int c = 0; c < 64; ++c) z2 += zp[c * NB + bb];
                float y0 = xc[bb], y1 = xc[NB + bb];
                out[(size_t)t * TRAJ + bb]      = y0;
                out[(size_t)t * TRAJ + NB + bb] = y1;
                out[CONBASE + (size_t)t * NB + bb] = bm1 * z2;
                xn[bb]      = a0 * y0 + a1 * y1 + bm0 * z2;
                xn[NB + bb] = a2 * y0 + a3 * y1 + bm1 * z2;
            }
        }
    }
    __syncthreads();

    // per-thread cp.async mapping: matrix = tid>>6, 8 (row,chunk) slots
    const int cmat = tid >> 6;
    const int clin = tid & 63;
    const char* gmat;
    if      (cmat == 0) gmat = (const char*)(g_Wh + (size_t)m0 * N);
    else if (cmat == 1) gmat = (const char*)(g_Wl + (size_t)m0 * N);
    else if (cmat == 2) gmat = (const char*)(hh + (size_t)b0t * N);
    else                gmat = (const char*)(hl + (size_t)b0t * N);
    const uint32_t sdstmat = sb + HDR + cmat * MATB;

    auto issue = [&](int ks) {
        uint32_t stb = sdstmat + (ks & 3) * STAGEB;
        size_t kb = (size_t)ks * (BK * 2);
#pragma unroll
        for (int it = 0; it < 8; ++it) {
            int idx = it * 64 + clin;
            int row = idx >> 2, chunk = idx & 3;
            cp16(stb + row * ROWB + chunk * 16,
                 gmat + (size_t)row * (N * 2) + kb + chunk * 16);
        }
    };

    // prologue stages
#pragma unroll
    for (int p = 0; p < 3; ++p) { issue(p); CPCOMMIT(); }

    float acc[4][4][4];
#pragma unroll
    for (int mi = 0; mi < 4; ++mi)
#pragma unroll
        for (int ni = 0; ni < 4; ++ni)
#pragma unroll
            for (int r = 0; r < 4; ++r) acc[mi][ni][r] = 0.0f;

    const int arow = wm * 64 + (lane >> 2);      // + mi*16 (+8)
    const int brow = wn * 32 + (lane >> 2);      // + ni*8
    const int cbyt = (lane & 3) * 4;             // frag col byte base (+kh*32, +16)

    for (int ks = 0; ks < KSTEPS; ++ks) {
        CPWAIT2();
        __syncthreads();
        if (ks + 3 < KSTEPS) issue(ks + 3);
        CPCOMMIT();

        const char* st = smem + HDR + (ks & 3) * STAGEB;
        const char* pAh = st;
        const char* pAl = st + MATB;
        const char* pBh = st + 2 * MATB;
        const char* pBl = st + 3 * MATB;

#pragma unroll
        for (int kh = 0; kh < 2; ++kh) {
            int cb = cbyt + kh * 32;
            uint32_t bh0[4], bh1[4], bl0[4], bl1[4];
#pragma unroll
            for (int ni = 0; ni < 4; ++ni) {
                int off = (brow + ni * 8) * ROWB + cb;
                bh0[ni] = *(const uint32_t*)(pBh + off);
                bh1[ni] = *(const uint32_t*)(pBh + off + 16);
                bl0[ni] = *(const uint32_t*)(pBl + off);
                bl1[ni] = *(const uint32_t*)(pBl + off + 16);
            }
#pragma unroll
            for (int mi = 0; mi < 4; ++mi) {
                int o0 = (arow + mi * 16) * ROWB + cb;
                int o1 = o0 + 8 * ROWB;
                uint32_t ah0 = *(const uint32_t*)(pAh + o0);
                uint32_t ah1 = *(const uint32_t*)(pAh + o1);
                uint32_t ah2 = *(const uint32_t*)(pAh + o0 + 16);
                uint32_t ah3 = *(const uint32_t*)(pAh + o1 + 16);
                uint32_t al0 = *(const uint32_t*)(pAl + o0);
                uint32_t al1 = *(const uint32_t*)(pAl + o1);
                uint32_t al2 = *(const uint32_t*)(pAl + o0 + 16);
                uint32_t al3 = *(const uint32_t*)(pAl + o1 + 16);
#pragma unroll
                for (int ni = 0; ni < 4; ++ni) {
                    MMA(acc[mi][ni], ah0, ah1, ah2, ah3, bh0[ni], bh1[ni]);
                    MMA(acc[mi][ni], ah0, ah1, ah2, ah3, bl0[ni], bl1[ni]);
                    MMA(acc[mi][ni], al0, al1, al2, al3, bh0[ni], bh1[ni]);
                }
            }
        }
    }
    __syncthreads();   // all compute done before Cs overwrites stage buffers

    // ---- Phase A: frags -> Cs (+ M[i]*cax[b]) ----
    float* Cs = reinterpret_cast<float*>(smem + HDR);
#pragma unroll
    for (int mi = 0; mi < 4; ++mi) {
#pragma unroll
        for (int ni = 0; ni < 4; ++ni) {
            int row = wm * 64 + mi * 16 + (lane >> 2);
            int col = wn * 32 + ni * 8 + (lane & 3) * 2;
            float* c = acc[mi][ni];
            float2 v0 = make_float2(c[0] + m_s[row] * cax_s[col],
                                    c[1] + m_s[row] * cax_s[col + 1]);
            float2 v1 = make_float2(c[2] + m_s[row + 8] * cax_s[col],
                                    c[3] + m_s[row + 8] * cax_s[col + 1]);
            *reinterpret_cast<float2*>(&Cs[row * CSTRIDE + col]) = v0;
            *reinterpret_cast<float2*>(&Cs[(row + 8) * CSTRIDE + col]) = v1;
        }
    }
    __syncthreads();

    // ---- Phase B: traj_{t+1} h rows (row-major, float4) ----
    {
        int row = tid >> 1;
        int cb = (tid & 1) * 64;
        const float* src = Cs + row * CSTRIDE + cb;
        float* dst = out + (size_t)(t + 1) * TRAJ + (size_t)(2 + m0 + row) * NB + b0t + cb;
#pragma unroll
        for (int j = 0; j < 64; j += 4)
            *reinterpret_cast<float4*>(dst + j) = *reinterpret_cast<const float4*>(src + j);
    }

    // ---- Phase C: transposed bf16 split + Z·h partials ----
    {
        int b = tid >> 1;
        int rb = (tid & 1) * 64;
        size_t base = (size_t)(b0t + b) * N + m0 + rb;
        uint32_t* ohp = reinterpret_cast<uint32_t*>(oh + base);
        uint32_t* olp = reinterpret_cast<uint32_t*>(ol + base);
        float zh = 0.0f;
#pragma unroll
        for (int r = 0; r < 64; r += 2) {
            float v0 = Cs[(rb + r) * CSTRIDE + b];
            float v1 = Cs[(rb + r + 1) * CSTRIDE + b];
            zh += z_s[rb + r] * v0 + z_s[rb + r + 1] * v1;
            __nv_bfloat16 h0 = __float2bfloat16(v0);
            __nv_bfloat16 h1 = __float2bfloat16(v1);
            __nv_bfloat16 l0 = __float2bfloat16(v0 - __bfloat162float(h0));
            __nv_bfloat16 l1 = __float2bfloat16(v1 - __bfloat162float(h1));
            ohp[r >> 1] = (uint32_t)__bfloat16_as_ushort(h0)
                        | ((uint32_t)__bfloat16_as_ushort(h1) << 16);
            olp[r >> 1] = (uint32_t)__bfloat16_as_ushort(l0)
                        | ((uint32_t)__bfloat16_as_ushort(l1) << 16);
        }
        g_zp[nxt][(mt * 2 + (tid & 1)) * NB + b0t + b] = zh;
    }
}

// ---------------- launch ----------------
extern "C" void kernel_launch(void* const* d_in, const int* in_sizes, int n_in,
                              void* d_out, int out_size)
{
    const float* x0 = (const float*)d_in[0];
    const float* x1 = (const float*)d_in[1];
    const float* h0 = (const float*)d_in[2];
    const float* A  = (const float*)d_in[3];
    const float* Bm = (const float*)d_in[4];
    const float* C  = (const float*)d_in[5];
    const float* M  = (const float*)d_in[6];
    const float* Z  = (const float*)d_in[7];
    const float* U  = (const float*)d_in[8];
    const float* V  = (const float*)d_in[9];
    const float* W  = (const float*)d_in[10];
    (void)in_sizes; (void)n_in; (void)out_size;
    float* out = (float*)d_out;

    cudaFuncSetAttribute(gemm_step, cudaFuncAttributeMaxDynamicSharedMemorySize, SMEMSZ);

    build_wp<<<dim3(N / 256, N), 256>>>(W, M, Z, U, V, Bm, C);
    init_h<<<dim3(N / 32, NB / 32), dim3(32, 8)>>>(h0, out);
    init_zx<<<dim3(64, 4), 128>>>(h0, Z, x0, x1);

    for (int t = 0; t < NSTEPS - 1; ++t)
        gemm_step<<<dim3(NB / BN, N / BM), 256, SMEMSZ>>>(t & 1, A, Bm, C, M, Z, out, t);

    final_xcon<<<1, 512>>>(Bm, out);
}